// round 17
// baseline (speedup 1.0000x reference)
#include <cuda_runtime.h>
#include <cstdint>

// Depthwise 3x3 (center tap zero) + residual, NHWC x[32,56,56,256] fp32.
// R3/R10/R16: three architectures converge at ~5.1TB/s, ~30us ncu ->
// bound by DRAM traffic mix (~103MB compulsory writes + ~57MB read misses;
// x is 103MB vs 126MB L2). R17 = R14 (best bench: rotating mod-6 float2
// window + __stcs) with ONE change: x reads carry an L2::evict_last
// cache-hint policy so x lines win residency against the write stream and
// survive across rows/blocks/graph-replays -> fewer DRAM read misses.

#define Bn 32
#define Hn 56
#define Wn 56
#define C2 128   // 256 channels / 2 per float2

__device__ __forceinline__ float2 f2fma(float2 k, float2 v, float2 a) {
    a.x = fmaf(k.x, v.x, a.x);
    a.y = fmaf(k.y, v.y, a.y);
    return a;
}

// ld.global.nc.v2.f32 with L2 evict_last cache-hint policy
__device__ __forceinline__ float2 ldg_el(const float2* p, uint64_t pol) {
    float2 r;
    asm volatile("ld.global.nc.L2::cache_hint.v2.f32 {%0, %1}, [%2], %3;"
                 : "=f"(r.x), "=f"(r.y) : "l"(p), "l"(pol));
    return r;
}

__global__ __launch_bounds__(256, 3)
void contour_integration_kernel(const float2* __restrict__ x,
                                const float2* __restrict__ k,
                                float2* __restrict__ out)
{
    const int c2 = threadIdx.x;                    // 0..127 channel pair
    const int bh = blockIdx.x * 2 + threadIdx.y;   // 0..B*H-1
    const int h  = bh % Hn;

    const float2 Z = make_float2(0.f, 0.f);

    // L2 evict_last policy for x reads (x ~fits in L2; keep it resident)
    uint64_t pol;
    asm volatile("createpolicy.fractional.L2::evict_last.b64 %0, 1.0;"
                 : "=l"(pol));

    // taps (cross-correlation; center k[1][1] excluded)
    float2 k00 = __ldg(&k[0 * C2 + c2]);
    float2 k01 = __ldg(&k[1 * C2 + c2]);
    float2 k02 = __ldg(&k[2 * C2 + c2]);
    float2 k10 = __ldg(&k[3 * C2 + c2]);
    float2 k12 = __ldg(&k[5 * C2 + c2]);
    float2 k20 = __ldg(&k[6 * C2 + c2]);
    float2 k21 = __ldg(&k[7 * C2 + c2]);
    float2 k22 = __ldg(&k[8 * C2 + c2]);

    // boundary rows: zero taps + clamped row pointers -> loads unconditional
    const bool hm = (h > 0);
    const bool hp = (h < Hn - 1);
    if (!hm) { k00 = Z; k01 = Z; k02 = Z; }
    if (!hp) { k20 = Z; k21 = Z; k22 = Z; }

    const int base = bh * Wn * C2 + c2;            // 32-bit safe
    const float2* __restrict__ row1 = x + base;
    const float2* __restrict__ row0 = hm ? (row1 - Wn * C2) : row1;
    const float2* __restrict__ row2 = hp ? (row1 + Wn * C2) : row1;
    float2* __restrict__ orow = out + base;

    // rotating window: slot(col) = (col + 1) % 6
    float2 win[3][6];

    // prologue: col -1 = Z (slot 0), cols 0..4 -> slots 1..5
    win[0][0] = Z; win[1][0] = Z; win[2][0] = Z;
    #pragma unroll
    for (int p = 1; p <= 5; ++p) {
        const int wc = (p - 1) * C2;
        win[0][p] = ldg_el(&row0[wc], pol);
        win[1][p] = ldg_el(&row1[wc], pol);
        win[2][p] = ldg_el(&row2[wc], pol);
    }

    #pragma unroll
    for (int w = 0; w < Wn; ++w) {
        const int s0 = w % 6;          // col w-1
        const int s1 = (w + 1) % 6;    // col w
        const int s2 = (w + 2) % 6;    // col w+1

        float2 acc = win[1][s1];       // residual (center x)
        acc = f2fma(k00, win[0][s0], acc);
        acc = f2fma(k01, win[0][s1], acc);
        acc = f2fma(k02, win[0][s2], acc);
        acc = f2fma(k10, win[1][s0], acc);
        acc = f2fma(k12, win[1][s2], acc);
        acc = f2fma(k20, win[2][s0], acc);
        acc = f2fma(k21, win[2][s1], acc);
        acc = f2fma(k22, win[2][s2], acc);
        __stcs(&orow[w * C2], acc);    // streaming store: evict-first in L2

        // slot s0 is now free: refill with column w+5 (first used at w+4)
        if (w < Wn - 5) {                          // compile-time (unrolled)
            const int wc = (w + 5) * C2;
            win[0][s0] = ldg_el(&row0[wc], pol);
            win[1][s0] = ldg_el(&row1[wc], pol);
            win[2][s0] = ldg_el(&row2[wc], pol);
        } else if (w == Wn - 5) {
            // phantom col 56 (right edge) must read as zero at w = 55
            win[0][s0] = Z; win[1][s0] = Z; win[2][s0] = Z;
        }
    }
}

extern "C" void kernel_launch(void* const* d_in, const int* in_sizes, int n_in,
                              void* d_out, int out_size)
{
    const float2* x = (const float2*)d_in[0];   // [32,56,56,256] fp32
    const float2* k = (const float2*)d_in[1];   // [3,3,256] fp32
    float2* out = (float2*)d_out;

    dim3 block(C2, 2);          // 256 threads: two full rows per block
    dim3 grid(Bn * Hn / 2);     // 896 blocks
    contour_integration_kernel<<<grid, block>>>(x, k, out);
}